// round 3
// baseline (speedup 1.0000x reference)
#include <cuda_runtime.h>
#include <cuda_bf16.h>

// Problem constants
#define BB 8
#define CC 256
#define HH 128
#define WW 128
#define BH (BB*HH)          // 1024 scanlines
#define HW (HH*WW)          // 16384
#define SROW 768            // scratch row pitch: [Q(256) | K(256) | V(256)]
#define SCAN (WW*SROW)      // 98304 floats per scanline

#define APITCH 260          // A^T smem pitch (kernel1)
#define KPITCH 260          // K smem pitch (kernel2, phase S)
#define VPITCH 264          // V smem pitch (kernel2, phase PV)
#define PPITCH 132          // P smem pitch

// 402 MB fp32 scratch for Q,K,V — static __device__ (no allocation allowed)
__device__ float g_S[BH * WW * SROW];

__device__ __forceinline__ unsigned f2tf(float f) {
    unsigned u;
    asm("cvt.rna.tf32.f32 %0, %1;" : "=r"(u) : "f"(f));
    return u;
}

__device__ __forceinline__ void mma_tf32(float* d, const unsigned* a, const unsigned* b) {
    asm volatile(
        "mma.sync.aligned.m16n8k8.row.col.f32.tf32.tf32.f32 "
        "{%0,%1,%2,%3}, {%4,%5,%6,%7}, {%8,%9}, {%0,%1,%2,%3};\n"
        : "+f"(d[0]), "+f"(d[1]), "+f"(d[2]), "+f"(d[3])
        : "r"(a[0]), "r"(a[1]), "r"(a[2]), "r"(a[3]), "r"(b[0]), "r"(b[1]));
}

// ---------------------------------------------------------------------------
// Kernel 1: QKV projection. One CTA per (b,h) scanline.
// Y[w, o] = sum_c A[b,c,h,w] * W[o,c] + bias[o],  o in [0,768)
// ---------------------------------------------------------------------------
extern "C" __global__ void __launch_bounds__(256, 1) qkv_proj(
    const float* __restrict__ a,
    const float* __restrict__ wq, const float* __restrict__ bq,
    const float* __restrict__ wk, const float* __restrict__ bk,
    const float* __restrict__ wv, const float* __restrict__ bv)
{
    extern __shared__ float As[];  // [WW][APITCH]
    const int bh  = blockIdx.x;
    const int tid = threadIdx.x;
    const float* ap = a + (size_t)(bh >> 7) * (CC * HW) + (size_t)(bh & 127) * WW;

    // Load A^T: As[w][c] = a[b, c, h, w]  (coalesced global reads)
    for (int i = tid; i < CC * WW; i += 256) {
        int c = i >> 7, w = i & 127;
        As[w * APITCH + c] = ap[(size_t)c * HW + w];
    }
    __syncthreads();

    const int warp = tid >> 5, lane = tid & 31;
    const int wm = warp >> 2, wn = warp & 3;   // 2 x 4 warp grid over 128 x 128
    const int g = lane >> 2, q = lane & 3;
    float* outp = g_S + (size_t)bh * SCAN;

    for (int chunk = 0; chunk < 6; chunk++) {
        const float* Wm   = (chunk < 2) ? wq : (chunk < 4 ? wk : wv);
        const float* bias = (chunk < 2) ? bq : (chunk < 4 ? bk : bv);
        const int cloc = (chunk & 1) * 128;   // column offset within the 256-col W

        float acc[16][4];
        #pragma unroll
        for (int i = 0; i < 16; i++)
            #pragma unroll
            for (int j = 0; j < 4; j++) acc[i][j] = 0.f;

        // B-fragment double buffer (weights from L2)
        unsigned bb[2][4][2];
        #pragma unroll
        for (int ni = 0; ni < 4; ni++) {
            int o = cloc + wn * 32 + ni * 8 + g;
            bb[0][ni][0] = f2tf(Wm[o * 256 + q]);
            bb[0][ni][1] = f2tf(Wm[o * 256 + 4 + q]);
        }
        int buf = 0;
        for (int kk = 0; kk < 256; kk += 8) {
            if (kk + 8 < 256) {
                #pragma unroll
                for (int ni = 0; ni < 4; ni++) {
                    int o = cloc + wn * 32 + ni * 8 + g;
                    bb[buf ^ 1][ni][0] = f2tf(Wm[o * 256 + kk + 8 + q]);
                    bb[buf ^ 1][ni][1] = f2tf(Wm[o * 256 + kk + 12 + q]);
                }
            }
            unsigned af[4][4];
            #pragma unroll
            for (int mi = 0; mi < 4; mi++) {
                int r = wm * 64 + mi * 16 + g;
                af[mi][0] = f2tf(As[r * APITCH + kk + q]);
                af[mi][1] = f2tf(As[(r + 8) * APITCH + kk + q]);
                af[mi][2] = f2tf(As[r * APITCH + kk + 4 + q]);
                af[mi][3] = f2tf(As[(r + 8) * APITCH + kk + 4 + q]);
            }
            #pragma unroll
            for (int mi = 0; mi < 4; mi++)
                #pragma unroll
                for (int ni = 0; ni < 4; ni++)
                    mma_tf32(acc[mi * 4 + ni], af[mi], bb[buf][ni]);
            buf ^= 1;
        }

        // Epilogue: bias add, store to scratch [w][768]
        #pragma unroll
        for (int mi = 0; mi < 4; mi++) {
            int r = wm * 64 + mi * 16 + g;
            #pragma unroll
            for (int ni = 0; ni < 4; ni++) {
                int oc = wn * 32 + ni * 8 + q * 2;   // col within chunk
                int o  = chunk * 128 + oc;           // global col 0..767
                int ob = cloc + oc;                  // col within bias vector
                float b0 = bias[ob], b1 = bias[ob + 1];
                float2 v0 = make_float2(acc[mi * 4 + ni][0] + b0, acc[mi * 4 + ni][1] + b1);
                float2 v1 = make_float2(acc[mi * 4 + ni][2] + b0, acc[mi * 4 + ni][3] + b1);
                *(float2*)(outp + r * SROW + o)       = v0;
                *(float2*)(outp + (r + 8) * SROW + o) = v1;
            }
        }
    }
}

// ---------------------------------------------------------------------------
// Kernel 2: per-scanline attention + residual. One CTA per (b,h).
//   S = Q K^T / 16 ; P = softmax_rows(S) ; O = P V ; out = a + O * Wp
// ---------------------------------------------------------------------------
extern "C" __global__ void __launch_bounds__(256, 1) attn_kernel(
    const float* __restrict__ a, const float* __restrict__ Wp,
    float* __restrict__ out)
{
    extern __shared__ float sm[];
    float* KV       = sm;            // 33792 floats: K (pitch 260) then V (pitch 264)
    float* P        = sm + 33792;    // 16896 floats: [128][132]
    float* rowScale = P + 16896;     // 128 floats

    const int bh  = blockIdx.x;
    const int tid = threadIdx.x;
    const int b = bh >> 7, h = bh & 127;
    const float* scan = g_S + (size_t)bh * SCAN;

    // Load K (cols 256..511) into KV with pitch 260
    for (int i = tid; i < WW * 64; i += 256) {
        int w = i >> 6, c4 = i & 63;
        float4 v = *(const float4*)(scan + w * SROW + 256 + c4 * 4);
        *(float4*)(KV + w * KPITCH + c4 * 4) = v;
    }
    __syncthreads();

    const int warp = tid >> 5, lane = tid & 31;
    const int wm = warp >> 1, wn = warp & 1;   // 4 x 2 warp grid
    const int g = lane >> 2, q = lane & 3;

    // ---- Phase S: S = Q K^T ----
    float s[16][4];   // 2 mi x 8 ni
    #pragma unroll
    for (int i = 0; i < 16; i++)
        #pragma unroll
        for (int j = 0; j < 4; j++) s[i][j] = 0.f;

    unsigned ab[2][2][4];   // Q fragments, double-buffered (from global)
    #pragma unroll
    for (int mi = 0; mi < 2; mi++) {
        int r = wm * 32 + mi * 16 + g;
        ab[0][mi][0] = f2tf(scan[r * SROW + q]);
        ab[0][mi][1] = f2tf(scan[(r + 8) * SROW + q]);
        ab[0][mi][2] = f2tf(scan[r * SROW + 4 + q]);
        ab[0][mi][3] = f2tf(scan[(r + 8) * SROW + 4 + q]);
    }
    int buf = 0;
    for (int kk = 0; kk < 256; kk += 8) {
        if (kk + 8 < 256) {
            #pragma unroll
            for (int mi = 0; mi < 2; mi++) {
                int r = wm * 32 + mi * 16 + g;
                ab[buf ^ 1][mi][0] = f2tf(scan[r * SROW + kk + 8 + q]);
                ab[buf ^ 1][mi][1] = f2tf(scan[(r + 8) * SROW + kk + 8 + q]);
                ab[buf ^ 1][mi][2] = f2tf(scan[r * SROW + kk + 12 + q]);
                ab[buf ^ 1][mi][3] = f2tf(scan[(r + 8) * SROW + kk + 12 + q]);
            }
        }
        unsigned bf[8][2];
        #pragma unroll
        for (int ni = 0; ni < 8; ni++) {
            int j = wn * 64 + ni * 8 + g;   // key index
            bf[ni][0] = f2tf(KV[j * KPITCH + kk + q]);
            bf[ni][1] = f2tf(KV[j * KPITCH + kk + 4 + q]);
        }
        #pragma unroll
        for (int mi = 0; mi < 2; mi++)
            #pragma unroll
            for (int ni = 0; ni < 8; ni++)
                mma_tf32(s[mi * 8 + ni], ab[buf][mi], bf[ni]);
        buf ^= 1;
    }

    // Scaled scores -> P smem
    const float scale = 0.0625f;   // 1/sqrt(256)
    #pragma unroll
    for (int mi = 0; mi < 2; mi++) {
        int r = wm * 32 + mi * 16 + g;
        #pragma unroll
        for (int ni = 0; ni < 8; ni++) {
            int c0 = wn * 64 + ni * 8 + q * 2;
            P[r * PPITCH + c0]           = s[mi * 8 + ni][0] * scale;
            P[r * PPITCH + c0 + 1]       = s[mi * 8 + ni][1] * scale;
            P[(r + 8) * PPITCH + c0]     = s[mi * 8 + ni][2] * scale;
            P[(r + 8) * PPITCH + c0 + 1] = s[mi * 8 + ni][3] * scale;
        }
    }
    __syncthreads();   // P complete; all K reads done

    // Load V (cols 512..767) into KV with pitch 264 (overwrites K)
    for (int i = tid; i < WW * 64; i += 256) {
        int w = i >> 6, c4 = i & 63;
        float4 v = *(const float4*)(scan + w * SROW + 512 + c4 * 4);
        *(float4*)(KV + w * VPITCH + c4 * 4) = v;
    }
    // Softmax: one thread per row; store un-normalized exp + reciprocal sum
    if (tid < 128) {
        float* row = P + tid * PPITCH;
        float m = row[0];
        #pragma unroll 4
        for (int j = 1; j < 128; j++) m = fmaxf(m, row[j]);
        float ssum = 0.f;
        #pragma unroll 4
        for (int j = 0; j < 128; j++) {
            float e = __expf(row[j] - m);
            row[j] = e;
            ssum += e;
        }
        rowScale[tid] = 1.0f / ssum;
    }
    __syncthreads();

    // ---- Phase PV: O = P V, fused epilogue out = a + O*rowScale*Wp ----
    const float wp = Wp[0];
    const size_t obase = (size_t)b * (CC * HW) + (size_t)h * WW;

    for (int nc = 0; nc < 2; nc++) {
        const int cb = nc * 128;
        float o[16][4];
        #pragma unroll
        for (int i = 0; i < 16; i++)
            #pragma unroll
            for (int j = 0; j < 4; j++) o[i][j] = 0.f;

        for (int kk = 0; kk < 128; kk += 8) {
            unsigned pa[2][4];
            #pragma unroll
            for (int mi = 0; mi < 2; mi++) {
                int r = wm * 32 + mi * 16 + g;
                pa[mi][0] = f2tf(P[r * PPITCH + kk + q]);
                pa[mi][1] = f2tf(P[(r + 8) * PPITCH + kk + q]);
                pa[mi][2] = f2tf(P[r * PPITCH + kk + 4 + q]);
                pa[mi][3] = f2tf(P[(r + 8) * PPITCH + kk + 4 + q]);
            }
            unsigned vb[8][2];
            #pragma unroll
            for (int ni = 0; ni < 8; ni++) {
                int c = cb + wn * 64 + ni * 8 + g;
                vb[ni][0] = f2tf(KV[(kk + q) * VPITCH + c]);
                vb[ni][1] = f2tf(KV[(kk + 4 + q) * VPITCH + c]);
            }
            #pragma unroll
            for (int mi = 0; mi < 2; mi++)
                #pragma unroll
                for (int ni = 0; ni < 8; ni++)
                    mma_tf32(o[mi * 8 + ni], pa[mi], vb[ni]);
        }

        // Epilogue: residual + scale, NCHW scatter (32B-sector friendly)
        #pragma unroll
        for (int mi = 0; mi < 2; mi++) {
            int r = wm * 32 + mi * 16 + g;
            float rs0 = rowScale[r] * wp;
            float rs1 = rowScale[r + 8] * wp;
            #pragma unroll
            for (int ni = 0; ni < 8; ni++) {
                int c0 = cb + wn * 64 + ni * 8 + q * 2;
                size_t i00 = obase + (size_t)c0 * HW + r;
                size_t i01 = obase + (size_t)(c0 + 1) * HW + r;
                out[i00]     = a[i00]     + o[mi * 8 + ni][0] * rs0;
                out[i01]     = a[i01]     + o[mi * 8 + ni][1] * rs0;
                out[i00 + 8] = a[i00 + 8] + o[mi * 8 + ni][2] * rs1;
                out[i01 + 8] = a[i01 + 8] + o[mi * 8 + ni][3] * rs1;
            }
        }
    }
}

// ---------------------------------------------------------------------------
extern "C" void kernel_launch(void* const* d_in, const int* in_sizes, int n_in,
                              void* d_out, int out_size)
{
    const float* a  = (const float*)d_in[0];
    const float* wq = (const float*)d_in[1];
    const float* bq = (const float*)d_in[2];
    const float* wk = (const float*)d_in[3];
    const float* bk = (const float*)d_in[4];
    const float* wv = (const float*)d_in[5];
    const float* bv = (const float*)d_in[6];
    const float* Wp = (const float*)d_in[7];
    float* out = (float*)d_out;

    const int smem1 = WW * APITCH * 4;                  // 133120 B
    const int smem2 = (33792 + 16896 + 128) * 4;        // 203264 B
    cudaFuncSetAttribute(qkv_proj,    cudaFuncAttributeMaxDynamicSharedMemorySize, smem1);
    cudaFuncSetAttribute(attn_kernel, cudaFuncAttributeMaxDynamicSharedMemorySize, smem2);

    qkv_proj<<<BH, 256, smem1>>>(a, wq, bq, wk, bk, wv, bv);
    attn_kernel<<<BH, 256, smem2>>>(a, Wp, out);
}